// round 2
// baseline (speedup 1.0000x reference)
#include <cuda_runtime.h>

// Problem constants
#define DIMV   768
#define NBAT   4
#define NSEQ   2048
#define NHEAD  12
#define HDIM   64
#define MTOT   (NBAT*NSEQ)     // 8192
#define SCALEQ 0.125f          // 1/sqrt(64)

// Scratch (no allocations allowed): Q, K, V, attention output
__device__ float g_Q[MTOT * DIMV];
__device__ float g_K[MTOT * DIMV];
__device__ float g_V[MTOT * DIMV];
__device__ float g_O[MTOT * DIMV];

// ---------------------------------------------------------------------------
// GEMM core: C[128x64 tile] = A[8192,768] @ W[768,768] (+bias) (*scale)
// 256 threads, BK=16, 8x4 per thread (interleaved 16-stride mapping).
// ---------------------------------------------------------------------------
__device__ __forceinline__ void gemm_tile_128x64(
    const float* __restrict__ A,
    const float* __restrict__ W,
    float* __restrict__ C,
    int rowBase, int colBase,
    float scl, const float* __restrict__ bias)
{
    __shared__ float As[16][132];   // [k][row], padded
    __shared__ float Bs[16][64];    // [k][col]

    const int tx = threadIdx.x, ty = threadIdx.y;   // 16 x 16
    const int tid = ty * 16 + tx;

    float c[8][4] = {};

    for (int k0 = 0; k0 < DIMV; k0 += 16) {
        // A tile: 128 rows x 16 k  (2048 elems, 8 per thread)
        #pragma unroll
        for (int t = 0; t < 8; t++) {
            int idx = tid + t * 256;
            int r = idx >> 4, k = idx & 15;
            As[k][r] = A[(size_t)(rowBase + r) * DIMV + k0 + k];
        }
        // B tile: 16 k x 64 cols (coalesced, 4 per thread)
        #pragma unroll
        for (int t = 0; t < 4; t++) {
            int idx = tid + t * 256;
            int cc = idx & 63, k = idx >> 6;
            Bs[k][cc] = W[(size_t)(k0 + k) * DIMV + colBase + cc];
        }
        __syncthreads();

        #pragma unroll
        for (int k = 0; k < 16; k++) {
            float a[8], b[4];
            #pragma unroll
            for (int i = 0; i < 8; i++) a[i] = As[k][i * 16 + ty];
            #pragma unroll
            for (int j = 0; j < 4; j++) b[j] = Bs[k][j * 16 + tx];
            #pragma unroll
            for (int i = 0; i < 8; i++)
                #pragma unroll
                for (int j = 0; j < 4; j++)
                    c[i][j] += a[i] * b[j];
        }
        __syncthreads();
    }

    #pragma unroll
    for (int i = 0; i < 8; i++)
        #pragma unroll
        for (int j = 0; j < 4; j++) {
            int col = colBase + j * 16 + tx;
            float bv = bias ? bias[col] : 0.0f;
            C[(size_t)(rowBase + i * 16 + ty) * DIMV + col] = c[i][j] * scl + bv;
        }
}

// Fused QKV GEMM: blockIdx.z selects which weight/output.
__global__ __launch_bounds__(256) void qkv_gemm(
    const float* __restrict__ x,
    const float* __restrict__ Wq,
    const float* __restrict__ Wk,
    const float* __restrict__ Wv)
{
    const float* W;
    float* out;
    float scl;
    if (blockIdx.z == 0)      { W = Wq; out = g_Q; scl = SCALEQ; }
    else if (blockIdx.z == 1) { W = Wk; out = g_K; scl = 1.0f;   }
    else                      { W = Wv; out = g_V; scl = 1.0f;   }
    gemm_tile_128x64(x, W, out, blockIdx.y * 128, blockIdx.x * 64, scl, nullptr);
}

// Output projection + bias
__global__ __launch_bounds__(256) void proj_gemm(
    const float* __restrict__ Wp,
    const float* __restrict__ bp,
    float* __restrict__ out)
{
    gemm_tile_128x64(g_O, Wp, out, blockIdx.y * 128, blockIdx.x * 64, 1.0f, bp);
}

// ---------------------------------------------------------------------------
// Flash attention: one block = 128 query rows of one (b, h).
// Tiles of 128 keys, online softmax. 256 threads (16x16).
// Thread (tx,ty): S rows i*16+ty (8), S cols j*16+tx (8); O dims tx*4..+3.
// Smem rows padded to 68 floats (Q/K/V) and 132 floats (P) -> float4-clean.
// ---------------------------------------------------------------------------
#define QKV_PAD 68
#define P_PAD   132
#define ATTN_SMEM_FLOATS (3 * 128 * QKV_PAD + 128 * P_PAD)
#define ATTN_SMEM_BYTES  (ATTN_SMEM_FLOATS * 4)

__global__ __launch_bounds__(256) void attn_kernel()
{
    extern __shared__ float sm[];
    float* Qs = sm;                      // 128 x 68
    float* Ks = Qs + 128 * QKV_PAD;      // 128 x 68
    float* Vs = Ks + 128 * QKV_PAD;      // 128 x 68
    float* Ps = Vs + 128 * QKV_PAD;      // 128 x 132

    const int tx = threadIdx.x, ty = threadIdx.y;
    const int tid = ty * 16 + tx;
    const int b = blockIdx.z, h = blockIdx.y;
    const int qBase = blockIdx.x * 128;

    const float* Qg = g_Q + (size_t)(b * NSEQ) * DIMV + h * HDIM;
    const float* Kg = g_K + (size_t)(b * NSEQ) * DIMV + h * HDIM;
    const float* Vg = g_V + (size_t)(b * NSEQ) * DIMV + h * HDIM;
    float*       Og = g_O + (size_t)(b * NSEQ) * DIMV + h * HDIM;

    // Load Q tile (128 x 64) as float4s
    #pragma unroll
    for (int t = 0; t < 8; t++) {
        int idx = tid + t * 256;          // 0..2047 float4s
        int r = idx >> 4, c4 = idx & 15;
        *(float4*)(Qs + r * QKV_PAD + c4 * 4) =
            *(const float4*)(Qg + (size_t)(qBase + r) * DIMV + c4 * 4);
    }

    float m[8], l[8], o[8][4];
    #pragma unroll
    for (int i = 0; i < 8; i++) {
        m[i] = -1e30f; l[i] = 0.0f;
        o[i][0] = o[i][1] = o[i][2] = o[i][3] = 0.0f;
    }

    for (int kt = 0; kt < NSEQ / 128; kt++) {
        __syncthreads();   // previous PV done before overwriting K/V
        const int kBase = kt * 128;
        #pragma unroll
        for (int t = 0; t < 8; t++) {
            int idx = tid + t * 256;
            int r = idx >> 4, c4 = idx & 15;
            *(float4*)(Ks + r * QKV_PAD + c4 * 4) =
                *(const float4*)(Kg + (size_t)(kBase + r) * DIMV + c4 * 4);
            *(float4*)(Vs + r * QKV_PAD + c4 * 4) =
                *(const float4*)(Vg + (size_t)(kBase + r) * DIMV + c4 * 4);
        }
        __syncthreads();

        // S = Q K^T  (8x8 per thread), float4 over the 64-d contraction
        float s[8][8];
        #pragma unroll
        for (int i = 0; i < 8; i++)
            #pragma unroll
            for (int j = 0; j < 8; j++) s[i][j] = 0.0f;

        #pragma unroll
        for (int kk = 0; kk < 16; kk++) {
            float4 q4[8];
            #pragma unroll
            for (int i = 0; i < 8; i++)
                q4[i] = *(const float4*)(Qs + (i * 16 + ty) * QKV_PAD + kk * 4);
            #pragma unroll
            for (int j = 0; j < 8; j++) {
                float4 k4 = *(const float4*)(Ks + (j * 16 + tx) * QKV_PAD + kk * 4);
                #pragma unroll
                for (int i = 0; i < 8; i++)
                    s[i][j] += q4[i].x * k4.x + q4[i].y * k4.y
                             + q4[i].z * k4.z + q4[i].w * k4.w;
            }
        }

        // Online softmax per row (16-lane shuffle reductions within half-warp)
        #pragma unroll
        for (int i = 0; i < 8; i++) {
            float mx = s[i][0];
            #pragma unroll
            for (int j = 1; j < 8; j++) mx = fmaxf(mx, s[i][j]);
            #pragma unroll
            for (int off = 8; off >= 1; off >>= 1)
                mx = fmaxf(mx, __shfl_xor_sync(0xffffffffu, mx, off));

            float mnew = fmaxf(m[i], mx);
            float corr = __expf(m[i] - mnew);
            float ls = 0.0f;
            #pragma unroll
            for (int j = 0; j < 8; j++) {
                float p = __expf(s[i][j] - mnew);
                Ps[(i * 16 + ty) * P_PAD + j * 16 + tx] = p;
                ls += p;
            }
            #pragma unroll
            for (int off = 8; off >= 1; off >>= 1)
                ls += __shfl_xor_sync(0xffffffffu, ls, off);

            l[i] = l[i] * corr + ls;
            m[i] = mnew;
            #pragma unroll
            for (int d = 0; d < 4; d++) o[i][d] *= corr;
        }
        __syncthreads();   // Ps visible

        // O += P @ V, k unrolled x4, float4 everywhere
        #pragma unroll 4
        for (int kk = 0; kk < 32; kk++) {
            float4 v0 = *(const float4*)(Vs + (4 * kk + 0) * QKV_PAD + tx * 4);
            float4 v1 = *(const float4*)(Vs + (4 * kk + 1) * QKV_PAD + tx * 4);
            float4 v2 = *(const float4*)(Vs + (4 * kk + 2) * QKV_PAD + tx * 4);
            float4 v3 = *(const float4*)(Vs + (4 * kk + 3) * QKV_PAD + tx * 4);
            #pragma unroll
            for (int i = 0; i < 8; i++) {
                float4 p4 = *(const float4*)(Ps + (i * 16 + ty) * P_PAD + kk * 4);
                o[i][0] += p4.x * v0.x + p4.y * v1.x + p4.z * v2.x + p4.w * v3.x;
                o[i][1] += p4.x * v0.y + p4.y * v1.y + p4.z * v2.y + p4.w * v3.y;
                o[i][2] += p4.x * v0.z + p4.y * v1.z + p4.z * v2.z + p4.w * v3.z;
                o[i][3] += p4.x * v0.w + p4.y * v1.w + p4.z * v2.w + p4.w * v3.w;
            }
        }
    }

    // Normalize and store
    #pragma unroll
    for (int i = 0; i < 8; i++) {
        float inv = 1.0f / l[i];
        float4 r;
        r.x = o[i][0] * inv; r.y = o[i][1] * inv;
        r.z = o[i][2] * inv; r.w = o[i][3] * inv;
        *(float4*)(Og + (size_t)(qBase + i * 16 + ty) * DIMV + tx * 4) = r;
    }
}

// ---------------------------------------------------------------------------
extern "C" void kernel_launch(void* const* d_in, const int* in_sizes, int n_in,
                              void* d_out, int out_size)
{
    const float* x  = (const float*)d_in[0];
    const float* Wq = (const float*)d_in[1];
    const float* Wk = (const float*)d_in[2];
    const float* Wv = (const float*)d_in[3];
    const float* Wp = (const float*)d_in[4];
    const float* bp = (const float*)d_in[5];
    float* out = (float*)d_out;

    // 168 KB dynamic smem for the attention kernel (idempotent attribute set)
    cudaFuncSetAttribute(attn_kernel,
                         cudaFuncAttributeMaxDynamicSharedMemorySize,
                         ATTN_SMEM_BYTES);

    dim3 blk(16, 16);
    qkv_gemm<<<dim3(DIMV / 64, MTOT / 128, 3), blk>>>(x, Wq, Wk, Wv);
    attn_kernel<<<dim3(NSEQ / 128, NHEAD, NBAT), blk, ATTN_SMEM_BYTES>>>();
    proj_gemm<<<dim3(DIMV / 64, MTOT / 128, 1), blk>>>(Wp, bp, out);
}

// round 3
// speedup vs baseline: 1.2915x; 1.2915x over previous
#include <cuda_runtime.h>
#include <cstdint>

// Problem constants
#define DIMV   768
#define NBAT   4
#define NSEQ   2048
#define NHEAD  12
#define HDIM   64
#define MTOT   (NBAT*NSEQ)     // 8192
#define SCALEQ 0.125f          // 1/sqrt(64)

// Scratch (no allocations allowed): Q, K, V, attention output
__device__ float g_Q[MTOT * DIMV];
__device__ float g_K[MTOT * DIMV];
__device__ float g_V[MTOT * DIMV];
__device__ float g_O[MTOT * DIMV];

// ---------------------------------------------------------------------------
// tf32 helpers
// ---------------------------------------------------------------------------
__device__ __forceinline__ float tf32r(float x) {
    uint32_t u;
    asm("cvt.rna.tf32.f32 %0, %1;" : "=r"(u) : "f"(x));
    return __uint_as_float(u);
}

__device__ __forceinline__ void mma_tf32(float c[4], const uint32_t a[4], const uint32_t b[2]) {
    asm volatile(
        "mma.sync.aligned.m16n8k8.row.col.f32.tf32.tf32.f32 "
        "{%0,%1,%2,%3}, {%4,%5,%6,%7}, {%8,%9}, {%0,%1,%2,%3};"
        : "+f"(c[0]), "+f"(c[1]), "+f"(c[2]), "+f"(c[3])
        : "r"(a[0]), "r"(a[1]), "r"(a[2]), "r"(a[3]), "r"(b[0]), "r"(b[1]));
}

// ---------------------------------------------------------------------------
// 3xTF32 GEMM tile: C[128x128] = A[8192,768] @ W[768,768] (*scl, +bias)
// 256 threads = 8 warps (4M x 2N), warp tile 32x64, BK=32.
// Smem: Ah/Al [m][36] (pad -> frag banks 4g+t distinct),
//       Bh/Bl [k][136] (pad -> frag banks 8t+g distinct).
// Split: C = Ah*Bh + Ah*Bl + Al*Bh  (lo*lo term ~2^-22, negligible)
// ---------------------------------------------------------------------------
#define A_PAD 36
#define B_PAD 136
#define GEMM_SMEM_FLOATS (2*128*A_PAD + 2*32*B_PAD)
#define GEMM_SMEM_BYTES  (GEMM_SMEM_FLOATS * 4)

__device__ __forceinline__ void gemm3x_tile(
    const float* __restrict__ A,
    const float* __restrict__ W,
    float* __restrict__ C,
    int rowBase, int colBase,
    float scl, const float* __restrict__ bias)
{
    extern __shared__ float dsm[];
    float* Ah_s = dsm;                       // 128 x 36
    float* Al_s = Ah_s + 128 * A_PAD;
    float* Bh_s = Al_s + 128 * A_PAD;        // 32 x 136
    float* Bl_s = Bh_s + 32 * B_PAD;

    const int tid  = threadIdx.x;
    const int lane = tid & 31, warp = tid >> 5;
    const int warpM = (warp >> 1) * 32;      // 0,32,64,96
    const int warpN = (warp & 1) * 64;       // 0,64
    const int gid = lane >> 2;               // 0..7
    const int tig = lane & 3;                // 0..3

    float c[2][8][4];
    #pragma unroll
    for (int mt = 0; mt < 2; mt++)
        #pragma unroll
        for (int nt = 0; nt < 8; nt++)
            #pragma unroll
            for (int e = 0; e < 4; e++) c[mt][nt][e] = 0.0f;

    for (int k0 = 0; k0 < DIMV; k0 += 32) {
        // Stage A tile 128x32 (convert to hi/lo during store)
        #pragma unroll
        for (int i = 0; i < 4; i++) {
            int f = tid + i * 256;           // 0..1023 float4s
            int r = f >> 3, kq = (f & 7) << 2;
            float4 v = *(const float4*)(A + (size_t)(rowBase + r) * DIMV + k0 + kq);
            float4 h, l;
            h.x = tf32r(v.x); l.x = tf32r(v.x - h.x);
            h.y = tf32r(v.y); l.y = tf32r(v.y - h.y);
            h.z = tf32r(v.z); l.z = tf32r(v.z - h.z);
            h.w = tf32r(v.w); l.w = tf32r(v.w - h.w);
            *(float4*)(Ah_s + r * A_PAD + kq) = h;
            *(float4*)(Al_s + r * A_PAD + kq) = l;
        }
        // Stage B tile 32x128
        #pragma unroll
        for (int i = 0; i < 4; i++) {
            int f = tid + i * 256;
            int kr = f >> 5, nq = (f & 31) << 2;
            float4 v = *(const float4*)(W + (size_t)(k0 + kr) * DIMV + colBase + nq);
            float4 h, l;
            h.x = tf32r(v.x); l.x = tf32r(v.x - h.x);
            h.y = tf32r(v.y); l.y = tf32r(v.y - h.y);
            h.z = tf32r(v.z); l.z = tf32r(v.z - h.z);
            h.w = tf32r(v.w); l.w = tf32r(v.w - h.w);
            *(float4*)(Bh_s + kr * B_PAD + nq) = h;
            *(float4*)(Bl_s + kr * B_PAD + nq) = l;
        }
        __syncthreads();

        #pragma unroll
        for (int ks = 0; ks < 4; ks++) {
            const int kb = ks * 8;
            // A fragments (m16k8): a0(g,t) a1(g+8,t) a2(g,t+4) a3(g+8,t+4)
            uint32_t ah[2][4], al[2][4];
            #pragma unroll
            for (int mt = 0; mt < 2; mt++) {
                const int m0 = warpM + mt * 16 + gid;
                const float* ph = Ah_s + m0 * A_PAD + kb + tig;
                const float* pl = Al_s + m0 * A_PAD + kb + tig;
                ah[mt][0] = __float_as_uint(ph[0]);
                ah[mt][1] = __float_as_uint(ph[8 * A_PAD]);
                ah[mt][2] = __float_as_uint(ph[4]);
                ah[mt][3] = __float_as_uint(ph[8 * A_PAD + 4]);
                al[mt][0] = __float_as_uint(pl[0]);
                al[mt][1] = __float_as_uint(pl[8 * A_PAD]);
                al[mt][2] = __float_as_uint(pl[4]);
                al[mt][3] = __float_as_uint(pl[8 * A_PAD + 4]);
            }
            // B fragments (k8n8, col): b0(t,g) b1(t+4,g)
            uint32_t bh[8][2], bl[8][2];
            #pragma unroll
            for (int nt = 0; nt < 8; nt++) {
                const int n0 = warpN + nt * 8 + gid;
                const float* ph = Bh_s + (kb + tig) * B_PAD + n0;
                const float* pl = Bl_s + (kb + tig) * B_PAD + n0;
                bh[nt][0] = __float_as_uint(ph[0]);
                bh[nt][1] = __float_as_uint(ph[4 * B_PAD]);
                bl[nt][0] = __float_as_uint(pl[0]);
                bl[nt][1] = __float_as_uint(pl[4 * B_PAD]);
            }
            #pragma unroll
            for (int mt = 0; mt < 2; mt++)
                #pragma unroll
                for (int nt = 0; nt < 8; nt++) {
                    mma_tf32(c[mt][nt], ah[mt], bh[nt]);
                    mma_tf32(c[mt][nt], ah[mt], bl[nt]);
                    mma_tf32(c[mt][nt], al[mt], bh[nt]);
                }
        }
        __syncthreads();
    }

    // Epilogue: c0(g,2t) c1(g,2t+1) c2(g+8,2t) c3(g+8,2t+1)
    #pragma unroll
    for (int mt = 0; mt < 2; mt++) {
        const int r0 = rowBase + warpM + mt * 16 + gid;
        #pragma unroll
        for (int nt = 0; nt < 8; nt++) {
            const int col = colBase + warpN + nt * 8 + 2 * tig;
            float b0 = bias ? bias[col]     : 0.0f;
            float b1 = bias ? bias[col + 1] : 0.0f;
            float2 v0, v1;
            v0.x = c[mt][nt][0] * scl + b0; v0.y = c[mt][nt][1] * scl + b1;
            v1.x = c[mt][nt][2] * scl + b0; v1.y = c[mt][nt][3] * scl + b1;
            *(float2*)(C + (size_t)r0 * DIMV + col)       = v0;
            *(float2*)(C + (size_t)(r0 + 8) * DIMV + col) = v1;
        }
    }
}

// Fused QKV GEMM (blockIdx.z selects weight/output)
__global__ __launch_bounds__(256) void qkv_gemm_tc(
    const float* __restrict__ x,
    const float* __restrict__ Wq,
    const float* __restrict__ Wk,
    const float* __restrict__ Wv)
{
    const float* W;
    float* out;
    float scl;
    if (blockIdx.z == 0)      { W = Wq; out = g_Q; scl = SCALEQ; }
    else if (blockIdx.z == 1) { W = Wk; out = g_K; scl = 1.0f;   }
    else                      { W = Wv; out = g_V; scl = 1.0f;   }
    gemm3x_tile(x, W, out, blockIdx.y * 128, blockIdx.x * 128, scl, nullptr);
}

// Output projection + bias
__global__ __launch_bounds__(256) void proj_gemm_tc(
    const float* __restrict__ Wp,
    const float* __restrict__ bp,
    float* __restrict__ out)
{
    gemm3x_tile(g_O, Wp, out, blockIdx.y * 128, blockIdx.x * 128, 1.0f, bp);
}

// ---------------------------------------------------------------------------
// Flash attention (unchanged from passing round-2 kernel):
// one block = 128 query rows of one (b, h). Tiles of 128 keys, online softmax.
// 256 threads (16x16).
// ---------------------------------------------------------------------------
#define QKV_PAD 68
#define P_PAD   132
#define ATTN_SMEM_FLOATS (3 * 128 * QKV_PAD + 128 * P_PAD)
#define ATTN_SMEM_BYTES  (ATTN_SMEM_FLOATS * 4)

__global__ __launch_bounds__(256) void attn_kernel()
{
    extern __shared__ float sm[];
    float* Qs = sm;                      // 128 x 68
    float* Ks = Qs + 128 * QKV_PAD;      // 128 x 68
    float* Vs = Ks + 128 * QKV_PAD;      // 128 x 68
    float* Ps = Vs + 128 * QKV_PAD;      // 128 x 132

    const int tx = threadIdx.x, ty = threadIdx.y;
    const int tid = ty * 16 + tx;
    const int b = blockIdx.z, h = blockIdx.y;
    const int qBase = blockIdx.x * 128;

    const float* Qg = g_Q + (size_t)(b * NSEQ) * DIMV + h * HDIM;
    const float* Kg = g_K + (size_t)(b * NSEQ) * DIMV + h * HDIM;
    const float* Vg = g_V + (size_t)(b * NSEQ) * DIMV + h * HDIM;
    float*       Og = g_O + (size_t)(b * NSEQ) * DIMV + h * HDIM;

    #pragma unroll
    for (int t = 0; t < 8; t++) {
        int idx = tid + t * 256;
        int r = idx >> 4, c4 = idx & 15;
        *(float4*)(Qs + r * QKV_PAD + c4 * 4) =
            *(const float4*)(Qg + (size_t)(qBase + r) * DIMV + c4 * 4);
    }

    float m[8], l[8], o[8][4];
    #pragma unroll
    for (int i = 0; i < 8; i++) {
        m[i] = -1e30f; l[i] = 0.0f;
        o[i][0] = o[i][1] = o[i][2] = o[i][3] = 0.0f;
    }

    for (int kt = 0; kt < NSEQ / 128; kt++) {
        __syncthreads();
        const int kBase = kt * 128;
        #pragma unroll
        for (int t = 0; t < 8; t++) {
            int idx = tid + t * 256;
            int r = idx >> 4, c4 = idx & 15;
            *(float4*)(Ks + r * QKV_PAD + c4 * 4) =
                *(const float4*)(Kg + (size_t)(kBase + r) * DIMV + c4 * 4);
            *(float4*)(Vs + r * QKV_PAD + c4 * 4) =
                *(const float4*)(Vg + (size_t)(kBase + r) * DIMV + c4 * 4);
        }
        __syncthreads();

        float s[8][8];
        #pragma unroll
        for (int i = 0; i < 8; i++)
            #pragma unroll
            for (int j = 0; j < 8; j++) s[i][j] = 0.0f;

        #pragma unroll
        for (int kk = 0; kk < 16; kk++) {
            float4 q4[8];
            #pragma unroll
            for (int i = 0; i < 8; i++)
                q4[i] = *(const float4*)(Qs + (i * 16 + ty) * QKV_PAD + kk * 4);
            #pragma unroll
            for (int j = 0; j < 8; j++) {
                float4 k4 = *(const float4*)(Ks + (j * 16 + tx) * QKV_PAD + kk * 4);
                #pragma unroll
                for (int i = 0; i < 8; i++)
                    s[i][j] += q4[i].x * k4.x + q4[i].y * k4.y
                             + q4[i].z * k4.z + q4[i].w * k4.w;
            }
        }

        #pragma unroll
        for (int i = 0; i < 8; i++) {
            float mx = s[i][0];
            #pragma unroll
            for (int j = 1; j < 8; j++) mx = fmaxf(mx, s[i][j]);
            #pragma unroll
            for (int off = 8; off >= 1; off >>= 1)
                mx = fmaxf(mx, __shfl_xor_sync(0xffffffffu, mx, off));

            float mnew = fmaxf(m[i], mx);
            float corr = __expf(m[i] - mnew);
            float ls = 0.0f;
            #pragma unroll
            for (int j = 0; j < 8; j++) {
                float p = __expf(s[i][j] - mnew);
                Ps[(i * 16 + ty) * P_PAD + j * 16 + tx] = p;
                ls += p;
            }
            #pragma unroll
            for (int off = 8; off >= 1; off >>= 1)
                ls += __shfl_xor_sync(0xffffffffu, ls, off);

            l[i] = l[i] * corr + ls;
            m[i] = mnew;
            #pragma unroll
            for (int d = 0; d < 4; d++) o[i][d] *= corr;
        }
        __syncthreads();

        #pragma unroll 4
        for (int kk = 0; kk < 32; kk++) {
            float4 v0 = *(const float4*)(Vs + (4 * kk + 0) * QKV_PAD + tx * 4);
            float4 v1 = *(const float4*)(Vs + (4 * kk + 1) * QKV_PAD + tx * 4);
            float4 v2 = *(const float4*)(Vs + (4 * kk + 2) * QKV_PAD + tx * 4);
            float4 v3 = *(const float4*)(Vs + (4 * kk + 3) * QKV_PAD + tx * 4);
            #pragma unroll
            for (int i = 0; i < 8; i++) {
                float4 p4 = *(const float4*)(Ps + (i * 16 + ty) * P_PAD + kk * 4);
                o[i][0] += p4.x * v0.x + p4.y * v1.x + p4.z * v2.x + p4.w * v3.x;
                o[i][1] += p4.x * v0.y + p4.y * v1.y + p4.z * v2.y + p4.w * v3.y;
                o[i][2] += p4.x * v0.z + p4.y * v1.z + p4.z * v2.z + p4.w * v3.z;
                o[i][3] += p4.x * v0.w + p4.y * v1.w + p4.z * v2.w + p4.w * v3.w;
            }
        }
    }

    #pragma unroll
    for (int i = 0; i < 8; i++) {
        float inv = 1.0f / l[i];
        float4 r;
        r.x = o[i][0] * inv; r.y = o[i][1] * inv;
        r.z = o[i][2] * inv; r.w = o[i][3] * inv;
        *(float4*)(Og + (size_t)(qBase + i * 16 + ty) * DIMV + tx * 4) = r;
    }
}

// ---------------------------------------------------------------------------
extern "C" void kernel_launch(void* const* d_in, const int* in_sizes, int n_in,
                              void* d_out, int out_size)
{
    const float* x  = (const float*)d_in[0];
    const float* Wq = (const float*)d_in[1];
    const float* Wk = (const float*)d_in[2];
    const float* Wv = (const float*)d_in[3];
    const float* Wp = (const float*)d_in[4];
    const float* bp = (const float*)d_in[5];
    float* out = (float*)d_out;

    cudaFuncSetAttribute(qkv_gemm_tc,
                         cudaFuncAttributeMaxDynamicSharedMemorySize,
                         GEMM_SMEM_BYTES);
    cudaFuncSetAttribute(proj_gemm_tc,
                         cudaFuncAttributeMaxDynamicSharedMemorySize,
                         GEMM_SMEM_BYTES);
    cudaFuncSetAttribute(attn_kernel,
                         cudaFuncAttributeMaxDynamicSharedMemorySize,
                         ATTN_SMEM_BYTES);

    qkv_gemm_tc<<<dim3(DIMV / 128, MTOT / 128, 3), 256, GEMM_SMEM_BYTES>>>(x, Wq, Wk, Wv);
    attn_kernel<<<dim3(NSEQ / 128, NHEAD, NBAT), dim3(16, 16), ATTN_SMEM_BYTES>>>();
    proj_gemm_tc<<<dim3(DIMV / 128, MTOT / 128, 1), 256, GEMM_SMEM_BYTES>>>(Wp, bp, out);
}

// round 6
// speedup vs baseline: 1.6909x; 1.3093x over previous
#include <cuda_runtime.h>
#include <cstdint>

// Problem constants
#define DIMV   768
#define NBAT   4
#define NSEQ   2048
#define NHEAD  12
#define HDIM   64
#define MTOT   (NBAT*NSEQ)     // 8192
#define SCALEQ 0.125f          // 1/sqrt(64)

// Scratch (no allocations allowed): Q, K, V, attention output
__device__ float g_Q[MTOT * DIMV];
__device__ float g_K[MTOT * DIMV];
__device__ float g_V[MTOT * DIMV];
__device__ float g_O[MTOT * DIMV];

// ---------------------------------------------------------------------------
// tf32 helpers
// ---------------------------------------------------------------------------
__device__ __forceinline__ float tf32r(float x) {
    uint32_t u;
    asm("cvt.rna.tf32.f32 %0, %1;" : "=r"(u) : "f"(x));
    return __uint_as_float(u);
}

__device__ __forceinline__ void mma_tf32(float c[4], const uint32_t a[4], const uint32_t b[2]) {
    asm volatile(
        "mma.sync.aligned.m16n8k8.row.col.f32.tf32.tf32.f32 "
        "{%0,%1,%2,%3}, {%4,%5,%6,%7}, {%8,%9}, {%0,%1,%2,%3};"
        : "+f"(c[0]), "+f"(c[1]), "+f"(c[2]), "+f"(c[3])
        : "r"(a[0]), "r"(a[1]), "r"(a[2]), "r"(a[3]), "r"(b[0]), "r"(b[1]));
}

// ---------------------------------------------------------------------------
// 3xTF32 GEMM tile: C[128x128] = A[8192,768] @ W[768,768] (*scl, +bias)
// 256 threads = 8 warps (4M x 2N), warp tile 32x64, BK=32.
// ---------------------------------------------------------------------------
#define A_PAD 36
#define B_PAD 136
#define GEMM_SMEM_FLOATS (2*128*A_PAD + 2*32*B_PAD)
#define GEMM_SMEM_BYTES  (GEMM_SMEM_FLOATS * 4)

__device__ __forceinline__ void gemm3x_tile(
    const float* __restrict__ A,
    const float* __restrict__ W,
    float* __restrict__ C,
    int rowBase, int colBase,
    float scl, const float* __restrict__ bias)
{
    extern __shared__ float dsm[];
    float* Ah_s = dsm;                       // 128 x 36
    float* Al_s = Ah_s + 128 * A_PAD;
    float* Bh_s = Al_s + 128 * A_PAD;        // 32 x 136
    float* Bl_s = Bh_s + 32 * B_PAD;

    const int tid  = threadIdx.x;
    const int lane = tid & 31, warp = tid >> 5;
    const int warpM = (warp >> 1) * 32;
    const int warpN = (warp & 1) * 64;
    const int gid = lane >> 2;
    const int tig = lane & 3;

    float c[2][8][4];
    #pragma unroll
    for (int mt = 0; mt < 2; mt++)
        #pragma unroll
        for (int nt = 0; nt < 8; nt++)
            #pragma unroll
            for (int e = 0; e < 4; e++) c[mt][nt][e] = 0.0f;

    for (int k0 = 0; k0 < DIMV; k0 += 32) {
        #pragma unroll
        for (int i = 0; i < 4; i++) {
            int f = tid + i * 256;
            int r = f >> 3, kq = (f & 7) << 2;
            float4 v = *(const float4*)(A + (size_t)(rowBase + r) * DIMV + k0 + kq);
            float4 h, l;
            h.x = tf32r(v.x); l.x = tf32r(v.x - h.x);
            h.y = tf32r(v.y); l.y = tf32r(v.y - h.y);
            h.z = tf32r(v.z); l.z = tf32r(v.z - h.z);
            h.w = tf32r(v.w); l.w = tf32r(v.w - h.w);
            *(float4*)(Ah_s + r * A_PAD + kq) = h;
            *(float4*)(Al_s + r * A_PAD + kq) = l;
        }
        #pragma unroll
        for (int i = 0; i < 4; i++) {
            int f = tid + i * 256;
            int kr = f >> 5, nq = (f & 31) << 2;
            float4 v = *(const float4*)(W + (size_t)(k0 + kr) * DIMV + colBase + nq);
            float4 h, l;
            h.x = tf32r(v.x); l.x = tf32r(v.x - h.x);
            h.y = tf32r(v.y); l.y = tf32r(v.y - h.y);
            h.z = tf32r(v.z); l.z = tf32r(v.z - h.z);
            h.w = tf32r(v.w); l.w = tf32r(v.w - h.w);
            *(float4*)(Bh_s + kr * B_PAD + nq) = h;
            *(float4*)(Bl_s + kr * B_PAD + nq) = l;
        }
        __syncthreads();

        #pragma unroll
        for (int ks = 0; ks < 4; ks++) {
            const int kb = ks * 8;
            uint32_t ah[2][4], al[2][4];
            #pragma unroll
            for (int mt = 0; mt < 2; mt++) {
                const int m0 = warpM + mt * 16 + gid;
                const float* ph = Ah_s + m0 * A_PAD + kb + tig;
                const float* pl = Al_s + m0 * A_PAD + kb + tig;
                ah[mt][0] = __float_as_uint(ph[0]);
                ah[mt][1] = __float_as_uint(ph[8 * A_PAD]);
                ah[mt][2] = __float_as_uint(ph[4]);
                ah[mt][3] = __float_as_uint(ph[8 * A_PAD + 4]);
                al[mt][0] = __float_as_uint(pl[0]);
                al[mt][1] = __float_as_uint(pl[8 * A_PAD]);
                al[mt][2] = __float_as_uint(pl[4]);
                al[mt][3] = __float_as_uint(pl[8 * A_PAD + 4]);
            }
            uint32_t bh[8][2], bl[8][2];
            #pragma unroll
            for (int nt = 0; nt < 8; nt++) {
                const int n0 = warpN + nt * 8 + gid;
                const float* ph = Bh_s + (kb + tig) * B_PAD + n0;
                const float* pl = Bl_s + (kb + tig) * B_PAD + n0;
                bh[nt][0] = __float_as_uint(ph[0]);
                bh[nt][1] = __float_as_uint(ph[4 * B_PAD]);
                bl[nt][0] = __float_as_uint(pl[0]);
                bl[nt][1] = __float_as_uint(pl[4 * B_PAD]);
            }
            #pragma unroll
            for (int mt = 0; mt < 2; mt++)
                #pragma unroll
                for (int nt = 0; nt < 8; nt++) {
                    mma_tf32(c[mt][nt], ah[mt], bh[nt]);
                    mma_tf32(c[mt][nt], ah[mt], bl[nt]);
                    mma_tf32(c[mt][nt], al[mt], bh[nt]);
                }
        }
        __syncthreads();
    }

    #pragma unroll
    for (int mt = 0; mt < 2; mt++) {
        const int r0 = rowBase + warpM + mt * 16 + gid;
        #pragma unroll
        for (int nt = 0; nt < 8; nt++) {
            const int col = colBase + warpN + nt * 8 + 2 * tig;
            float b0 = bias ? bias[col]     : 0.0f;
            float b1 = bias ? bias[col + 1] : 0.0f;
            float2 v0, v1;
            v0.x = c[mt][nt][0] * scl + b0; v0.y = c[mt][nt][1] * scl + b1;
            v1.x = c[mt][nt][2] * scl + b0; v1.y = c[mt][nt][3] * scl + b1;
            *(float2*)(C + (size_t)r0 * DIMV + col)       = v0;
            *(float2*)(C + (size_t)(r0 + 8) * DIMV + col) = v1;
        }
    }
}

__global__ __launch_bounds__(256) void qkv_gemm_tc(
    const float* __restrict__ x,
    const float* __restrict__ Wq,
    const float* __restrict__ Wk,
    const float* __restrict__ Wv)
{
    const float* W;
    float* out;
    float scl;
    if (blockIdx.z == 0)      { W = Wq; out = g_Q; scl = SCALEQ; }
    else if (blockIdx.z == 1) { W = Wk; out = g_K; scl = 1.0f;   }
    else                      { W = Wv; out = g_V; scl = 1.0f;   }
    gemm3x_tile(x, W, out, blockIdx.y * 128, blockIdx.x * 128, scl, nullptr);
}

__global__ __launch_bounds__(256) void proj_gemm_tc(
    const float* __restrict__ Wp,
    const float* __restrict__ bp,
    float* __restrict__ out)
{
    gemm3x_tile(g_O, Wp, out, blockIdx.y * 128, blockIdx.x * 128, 1.0f, bp);
}

// ---------------------------------------------------------------------------
// Tensor-core flash attention (3xTF32 for QK^T and PV).
// Block = 128 q rows of one (b,h); 256 thr = 8 warps; warp w owns rows 16w..16w+15
// (full score rows -> softmax reduce = 2 intra-quad shuffles, no cross-warp).
// KV processed in tiles of 64 keys. P relayout via smem (own-warp rows only).
// Pads: Q/K/P = 68 (A-frag & K-B-frag banks 4g+t distinct), V = 72 (8t+g distinct).
// ---------------------------------------------------------------------------
#define APAD 68
#define VPAD 72
#define KTILE 64
#define ATTN_SMEM_FLOATS (4*128*APAD + 2*KTILE*APAD + 2*KTILE*VPAD)
#define ATTN_SMEM_BYTES  (ATTN_SMEM_FLOATS * 4)   // 210,944 B

__global__ __launch_bounds__(256) void attn_tc()
{
    extern __shared__ float sm[];
    float* Qh = sm;                      // 128 x 68
    float* Ql = Qh + 128 * APAD;
    float* Ph = Ql + 128 * APAD;         // 128 x 68
    float* Pl = Ph + 128 * APAD;
    float* Kh = Pl + 128 * APAD;         // 64 x 68
    float* Kl = Kh + KTILE * APAD;
    float* Vh = Kl + KTILE * APAD;       // 64 x 72
    float* Vl = Vh + KTILE * VPAD;

    const int tid  = threadIdx.x;
    const int lane = tid & 31, warp = tid >> 5;
    const int gid = lane >> 2;           // 0..7
    const int tig = lane & 3;            // 0..3
    const int m0 = warp * 16;            // warp's q-row base within tile

    const int b = blockIdx.z, h = blockIdx.y;
    const int qBase = blockIdx.x * 128;

    const float* Qg = g_Q + (size_t)(b * NSEQ) * DIMV + h * HDIM;
    const float* Kg = g_K + (size_t)(b * NSEQ) * DIMV + h * HDIM;
    const float* Vg = g_V + (size_t)(b * NSEQ) * DIMV + h * HDIM;
    float*       Og = g_O + (size_t)(b * NSEQ) * DIMV + h * HDIM;

    // Load Q tile (128 x 64) with tf32 hi/lo split (Q already carries 1/sqrt(d))
    #pragma unroll
    for (int t = 0; t < 8; t++) {
        int idx = tid + t * 256;
        int r = idx >> 4, c4 = (idx & 15) << 2;
        float4 v = *(const float4*)(Qg + (size_t)(qBase + r) * DIMV + c4);
        float4 hi, lo;
        hi.x = tf32r(v.x); lo.x = tf32r(v.x - hi.x);
        hi.y = tf32r(v.y); lo.y = tf32r(v.y - hi.y);
        hi.z = tf32r(v.z); lo.z = tf32r(v.z - hi.z);
        hi.w = tf32r(v.w); lo.w = tf32r(v.w - hi.w);
        *(float4*)(Qh + r * APAD + c4) = hi;
        *(float4*)(Ql + r * APAD + c4) = lo;
    }

    float o[8][4];
    #pragma unroll
    for (int nt = 0; nt < 8; nt++)
        #pragma unroll
        for (int e = 0; e < 4; e++) o[nt][e] = 0.0f;
    float mrow[2] = {-1e30f, -1e30f};
    float lrow[2] = {0.0f, 0.0f};

    for (int kt = 0; kt < NSEQ / KTILE; kt++) {
        __syncthreads();                 // prior tile's K/V reads complete
        // Load K,V tile (64 x 64 each), hi/lo split
        #pragma unroll
        for (int t = 0; t < 4; t++) {
            int idx = tid + t * 256;
            int r = idx >> 4, c4 = (idx & 15) << 2;
            size_t g = (size_t)(kt * KTILE + r) * DIMV + c4;
            float4 kv = *(const float4*)(Kg + g);
            float4 vv = *(const float4*)(Vg + g);
            float4 hi, lo;
            hi.x = tf32r(kv.x); lo.x = tf32r(kv.x - hi.x);
            hi.y = tf32r(kv.y); lo.y = tf32r(kv.y - hi.y);
            hi.z = tf32r(kv.z); lo.z = tf32r(kv.z - hi.z);
            hi.w = tf32r(kv.w); lo.w = tf32r(kv.w - hi.w);
            *(float4*)(Kh + r * APAD + c4) = hi;
            *(float4*)(Kl + r * APAD + c4) = lo;
            hi.x = tf32r(vv.x); lo.x = tf32r(vv.x - hi.x);
            hi.y = tf32r(vv.y); lo.y = tf32r(vv.y - hi.y);
            hi.z = tf32r(vv.z); lo.z = tf32r(vv.z - hi.z);
            hi.w = tf32r(vv.w); lo.w = tf32r(vv.w - hi.w);
            *(float4*)(Vh + r * VPAD + c4) = hi;
            *(float4*)(Vl + r * VPAD + c4) = lo;
        }
        __syncthreads();

        // S = Q K^T : warp computes 16 x 64 scores (8 n-tiles)
        float s[8][4];
        #pragma unroll
        for (int nt = 0; nt < 8; nt++)
            #pragma unroll
            for (int e = 0; e < 4; e++) s[nt][e] = 0.0f;

        #pragma unroll
        for (int ks = 0; ks < 8; ks++) {
            const int kb = ks * 8;
            uint32_t qh[4], ql[4];
            {
                const float* ph = Qh + (m0 + gid) * APAD + kb + tig;
                const float* pl = Ql + (m0 + gid) * APAD + kb + tig;
                qh[0] = __float_as_uint(ph[0]);
                qh[1] = __float_as_uint(ph[8 * APAD]);
                qh[2] = __float_as_uint(ph[4]);
                qh[3] = __float_as_uint(ph[8 * APAD + 4]);
                ql[0] = __float_as_uint(pl[0]);
                ql[1] = __float_as_uint(pl[8 * APAD]);
                ql[2] = __float_as_uint(pl[4]);
                ql[3] = __float_as_uint(pl[8 * APAD + 4]);
            }
            #pragma unroll
            for (int nt = 0; nt < 8; nt++) {
                const int n0 = nt * 8 + gid;
                uint32_t bh[2], bl[2];
                bh[0] = __float_as_uint(Kh[n0 * APAD + kb + tig]);
                bh[1] = __float_as_uint(Kh[n0 * APAD + kb + tig + 4]);
                bl[0] = __float_as_uint(Kl[n0 * APAD + kb + tig]);
                bl[1] = __float_as_uint(Kl[n0 * APAD + kb + tig + 4]);
                mma_tf32(s[nt], qh, bh);
                mma_tf32(s[nt], qh, bl);
                mma_tf32(s[nt], ql, bh);
            }
        }

        // Online softmax: rows (m0+gid) [e=0,1] and (m0+8+gid) [e=2,3]
        float mx0 = -1e30f, mx1 = -1e30f;
        #pragma unroll
        for (int nt = 0; nt < 8; nt++) {
            mx0 = fmaxf(mx0, fmaxf(s[nt][0], s[nt][1]));
            mx1 = fmaxf(mx1, fmaxf(s[nt][2], s[nt][3]));
        }
        mx0 = fmaxf(mx0, __shfl_xor_sync(0xffffffffu, mx0, 1));
        mx0 = fmaxf(mx0, __shfl_xor_sync(0xffffffffu, mx0, 2));
        mx1 = fmaxf(mx1, __shfl_xor_sync(0xffffffffu, mx1, 1));
        mx1 = fmaxf(mx1, __shfl_xor_sync(0xffffffffu, mx1, 2));

        float mn0 = fmaxf(mrow[0], mx0);
        float mn1 = fmaxf(mrow[1], mx1);
        float cor0 = __expf(mrow[0] - mn0);
        float cor1 = __expf(mrow[1] - mn1);
        float ls0 = 0.0f, ls1 = 0.0f;

        const int r0 = m0 + gid, r1 = m0 + 8 + gid;
        #pragma unroll
        for (int nt = 0; nt < 8; nt++) {
            float p0 = __expf(s[nt][0] - mn0);
            float p1 = __expf(s[nt][1] - mn0);
            float p2 = __expf(s[nt][2] - mn1);
            float p3 = __expf(s[nt][3] - mn1);
            ls0 += p0 + p1;
            ls1 += p2 + p3;
            float h0 = tf32r(p0), h1 = tf32r(p1), h2 = tf32r(p2), h3 = tf32r(p3);
            int co = nt * 8 + 2 * tig;
            *(float2*)(Ph + r0 * APAD + co) = make_float2(h0, h1);
            *(float2*)(Ph + r1 * APAD + co) = make_float2(h2, h3);
            *(float2*)(Pl + r0 * APAD + co) = make_float2(tf32r(p0 - h0), tf32r(p1 - h1));
            *(float2*)(Pl + r1 * APAD + co) = make_float2(tf32r(p2 - h2), tf32r(p3 - h3));
        }
        ls0 += __shfl_xor_sync(0xffffffffu, ls0, 1);
        ls0 += __shfl_xor_sync(0xffffffffu, ls0, 2);
        ls1 += __shfl_xor_sync(0xffffffffu, ls1, 1);
        ls1 += __shfl_xor_sync(0xffffffffu, ls1, 2);

        lrow[0] = lrow[0] * cor0 + ls0;
        lrow[1] = lrow[1] * cor1 + ls1;
        mrow[0] = mn0; mrow[1] = mn1;
        #pragma unroll
        for (int nt = 0; nt < 8; nt++) {
            o[nt][0] *= cor0; o[nt][1] *= cor0;
            o[nt][2] *= cor1; o[nt][3] *= cor1;
        }
        __syncwarp();                    // P visible within warp (own rows only)

        // O += P V : M=16, N=64, K=64 (keys)
        #pragma unroll
        for (int ks = 0; ks < 8; ks++) {
            const int kb = ks * 8;
            uint32_t ph_[4], pl_[4];
            {
                const float* ph = Ph + (m0 + gid) * APAD + kb + tig;
                const float* pl = Pl + (m0 + gid) * APAD + kb + tig;
                ph_[0] = __float_as_uint(ph[0]);
                ph_[1] = __float_as_uint(ph[8 * APAD]);
                ph_[2] = __float_as_uint(ph[4]);
                ph_[3] = __float_as_uint(ph[8 * APAD + 4]);
                pl_[0] = __float_as_uint(pl[0]);
                pl_[1] = __float_as_uint(pl[8 * APAD]);
                pl_[2] = __float_as_uint(pl[4]);
                pl_[3] = __float_as_uint(pl[8 * APAD + 4]);
            }
            #pragma unroll
            for (int nt = 0; nt < 8; nt++) {
                const int n0 = nt * 8 + gid;
                uint32_t bh[2], bl[2];
                bh[0] = __float_as_uint(Vh[(kb + tig) * VPAD + n0]);
                bh[1] = __float_as_uint(Vh[(kb + tig + 4) * VPAD + n0]);
                bl[0] = __float_as_uint(Vl[(kb + tig) * VPAD + n0]);
                bl[1] = __float_as_uint(Vl[(kb + tig + 4) * VPAD + n0]);
                mma_tf32(o[nt], ph_, bh);
                mma_tf32(o[nt], ph_, bl);
                mma_tf32(o[nt], pl_, bh);
            }
        }
    }

    // Normalize and store (cols nt*8+2tig, rows m0+gid / +8)
    float inv0 = 1.0f / lrow[0], inv1 = 1.0f / lrow[1];
    const int gr0 = qBase + m0 + gid, gr1 = gr0 + 8;
    #pragma unroll
    for (int nt = 0; nt < 8; nt++) {
        int co = nt * 8 + 2 * tig;
        *(float2*)(Og + (size_t)gr0 * DIMV + co) =
            make_float2(o[nt][0] * inv0, o[nt][1] * inv0);
        *(float2*)(Og + (size_t)gr1 * DIMV + co) =
            make_float2(o[nt][2] * inv1, o[nt][3] * inv1);
    }
}

// ---------------------------------------------------------------------------
extern "C" void kernel_launch(void* const* d_in, const int* in_sizes, int n_in,
                              void* d_out, int out_size)
{
    const float* x  = (const float*)d_in[0];
    const float* Wq = (const float*)d_in[1];
    const float* Wk = (const float*)d_in[2];
    const float* Wv = (const float*)d_in[3];
    const float* Wp = (const float*)d_in[4];
    const float* bp = (const float*)d_in[5];
    float* out = (float*)d_out;

    cudaFuncSetAttribute(qkv_gemm_tc,
                         cudaFuncAttributeMaxDynamicSharedMemorySize,
                         GEMM_SMEM_BYTES);
    cudaFuncSetAttribute(proj_gemm_tc,
                         cudaFuncAttributeMaxDynamicSharedMemorySize,
                         GEMM_SMEM_BYTES);
    cudaFuncSetAttribute(attn_tc,
                         cudaFuncAttributeMaxDynamicSharedMemorySize,
                         ATTN_SMEM_BYTES);

    qkv_gemm_tc<<<dim3(DIMV / 128, MTOT / 128, 3), 256, GEMM_SMEM_BYTES>>>(x, Wq, Wk, Wv);
    attn_tc<<<dim3(NSEQ / 128, NHEAD, NBAT), 256, ATTN_SMEM_BYTES>>>();
    proj_gemm_tc<<<dim3(DIMV / 128, MTOT / 128, 1), 256, GEMM_SMEM_BYTES>>>(Wp, bp, out);
}